// round 7
// baseline (speedup 1.0000x reference)
#include <cuda_runtime.h>
#include <cuda_bf16.h>

#define S        8192
#define TPB      512
#define CHUNKS   (S / TPB)          // 16 positions per thread
#define NWARP    (TPB / 32)         // 16 warps
#define NW       (S / 32)           // 256 mask words per row
#define MAXROWS  2048

__device__ float    g_partial[MAXROWS];
__device__ float    g_count[MAXROWS];
__device__ unsigned g_done;          // zero-init; self-resets every pass

__global__ __launch_bounds__(TPB, 3)
void prox_loss_kernel(const float4* __restrict__ logits,
                      const int*    __restrict__ labels,
                      const float*  __restrict__ cw,
                      float*        __restrict__ out,
                      int nrows) {
    // M[0]=true2, M[1]=true3, M[2]=pred2, M[3]=pred3 (padded +1 both ends)
    __shared__ unsigned M[4][NW + 2];
    __shared__ float    lut[2048];               // f1 by 11-bit true-window
    __shared__ float    ws_sum[NWARP], ws_cnt[NWARP];
    __shared__ bool     s_is_last;

    const int row  = blockIdx.x;
    const int tid  = threadIdx.x;
    const int lane = tid & 31;
    const int warp = tid >> 5;

    const float NEG_LOG2_08 = -0.321928095f;     // log2(0.8)

    // ---- LUT + pad init (before the mask barrier) ----
    #pragma unroll
    for (int v = tid; v < 2048; v += TPB) {
        float f = 1.0f;
        if (!((v >> 5) & 1)) {                   // no true switch AT the position
            const unsigned fold = (__brev((unsigned)v & 31u) >> 27)
                                | (((unsigned)v >> 6) & 31u);  // bit(k-1)=dist k
            if (fold) f = exp2f((float)__ffs(fold) * NEG_LOG2_08);
        }
        lut[v] = f;
    }
    if (tid < 4) { M[tid][0] = 0u; M[tid][NW + 1] = 0u; }

    const float w0 = __ldg(&cw[0]);
    const float w1 = __ldg(&cw[1]);
    const float w2 = __ldg(&cw[2]);
    const float w3 = __ldg(&cw[3]);

    const float4* lg = logits + (size_t)row * S;
    const int*    lb = labels + (size_t)row * S;

    float    ce[CHUNKS];
    unsigned labPack  = 0u;    // per position: bit(2c+1)=tm, bit(2c)=y3
    unsigned predPack = 0u;    // per position: bit(2c+1)=pm, bit(2c)=a3
    float    cnt = 0.0f;

    // ---- Phase 1: load, CE -> regs, pred bools, ballot masks -> smem ----
    #pragma unroll
    for (int c = 0; c < CHUNKS; c++) {
        const int p = c * TPB + tid;
        const float4 l = lg[p];
        const int    y = lb[p];

        // first-occurrence argmax membership for classes 2/3 only
        const bool gwz = l.w > l.z;
        const bool p3b = (l.w > l.x) & (l.w > l.y) & gwz;
        const bool p2b = (l.z > l.x) & (l.z > l.y) & !gwz;

        // softmax without max-subtraction (logits ~ N(0,1): no overflow risk)
        const float esum = __expf(l.x) + __expf(l.y) + __expf(l.z) + __expf(l.w);
        const float lse  = __logf(esum);

        const int ys = (y < 0) ? 0 : y;
        const float lya = (ys & 1) ? l.y : l.x;
        const float lyb = (ys & 1) ? l.w : l.z;
        const float ly  = (ys & 2) ? lyb : lya;
        const float wya = (ys & 1) ? w1 : w0;
        const float wyb = (ys & 1) ? w3 : w2;
        const float wy  = (ys & 2) ? wyb : wya;
        ce[c] = (y < 0) ? 0.0f : wy * (lse - ly);

        const bool t3b = (y == 3);
        const bool tmb = (y == 2) | t3b;
        labPack  |= (((unsigned)tmb << 1) | (unsigned)t3b) << (2 * c);
        predPack |= (((unsigned)(p2b | p3b) << 1) | (unsigned)p3b) << (2 * c);

        const unsigned bt2 = __ballot_sync(0xFFFFFFFFu, y == 2);
        const unsigned bt3 = __ballot_sync(0xFFFFFFFFu, t3b);
        const unsigned bp2 = __ballot_sync(0xFFFFFFFFu, p2b);
        const unsigned bp3 = __ballot_sync(0xFFFFFFFFu, p3b);
        const unsigned bv  = __ballot_sync(0xFFFFFFFFu, y >= 0);
        if (lane == 0) {
            const int wi = (p >> 5) + 1;
            M[0][wi] = bt2; M[1][wi] = bt3; M[2][wi] = bp2; M[3][wi] = bp3;
            cnt += (float)__popc(bv);
        }
    }

    __syncthreads();

    // ---- any2/any3 from completed pred masks.
    //      NOTE: __syncthreads_or is a PREDICATE reduction (returns 0/nonzero),
    //      so each flag needs its own call. ----
    const int r3 = tid >> 8;                       // 0: scan pred2, 1: scan pred3
    const unsigned wv = M[2 + r3][(tid & 255) + 1];
    const int any2 = __syncthreads_or((int)((r3 == 0) && (wv != 0u)));
    const int any3 = __syncthreads_or((int)((r3 == 1) && (wv != 0u)));

    float sum = 0.0f;

    // ---- Phase 2: windows from smem + packed center bits from regs ----
    #pragma unroll
    for (int c = 0; c < CHUNKS; c++) {
        const int p   = c * TPB + tid;
        const unsigned yb = labPack  >> (2 * c);   // bit1=tm, bit0=y3
        const unsigned ab = predPack >> (2 * c);   // bit1=pm, bit0=a3

        const int bpp = p + 27;                    // padded bitspace start
        const int wi0 = bpp >> 5;
        const int sh  = bpp & 31;

        const unsigned arow = ab & 1u;
        const unsigned tw = __funnelshift_r(M[arow][wi0], M[arow][wi0 + 1], sh) & 0x7FFu;
        const unsigned prow = 2u + (yb & 1u);
        const unsigned pw = __funnelshift_r(M[prow][wi0], M[prow][wi0 + 1], sh) & 0x7FFu;

        const float f1 = (ab & 2u) ? lut[tw] : 1.0f;
        const int  anyc = (yb & 1u) ? any3 : any2;
        const float f2 = (yb & 2u) ? (anyc ? (pw ? 1.0f : 1.5f) : 2.0f) : 1.0f;

        sum += ce[c] * (f1 * f2);
    }

    // ---- Block reduction ----
    #pragma unroll
    for (int o = 16; o > 0; o >>= 1)
        sum += __shfl_down_sync(0xFFFFFFFFu, sum, o);
    if (lane == 0) { ws_sum[warp] = sum; ws_cnt[warp] = cnt; }
    __syncthreads();
    if (warp == 0) {
        sum = (lane < NWARP) ? ws_sum[lane] : 0.0f;
        cnt = (lane < NWARP) ? ws_cnt[lane] : 0.0f;
        #pragma unroll
        for (int o = 8; o > 0; o >>= 1) {
            sum += __shfl_down_sync(0xFFFFFFFFu, sum, o);
            cnt += __shfl_down_sync(0xFFFFFFFFu, cnt, o);
        }
        if (lane == 0) {
            g_partial[row] = sum;
            g_count[row]   = cnt;
            __threadfence();
            const unsigned prev = atomicAdd(&g_done, 1u);
            s_is_last = (prev == (unsigned)(nrows - 1));
        }
    }
    __syncthreads();

    // ---- Last block: global reduce + divide, reset counter ----
    if (s_is_last) {
        float s = 0.0f, c = 0.0f;
        for (int i = tid; i < nrows; i += TPB) {
            s += *((volatile float*)&g_partial[i]);
            c += *((volatile float*)&g_count[i]);
        }
        #pragma unroll
        for (int o = 16; o > 0; o >>= 1) {
            s += __shfl_down_sync(0xFFFFFFFFu, s, o);
            c += __shfl_down_sync(0xFFFFFFFFu, c, o);
        }
        if (lane == 0) { ws_sum[warp] = s; ws_cnt[warp] = c; }
        __syncthreads();
        if (warp == 0) {
            s = (lane < NWARP) ? ws_sum[lane] : 0.0f;
            c = (lane < NWARP) ? ws_cnt[lane] : 0.0f;
            #pragma unroll
            for (int o = 8; o > 0; o >>= 1) {
                s += __shfl_down_sync(0xFFFFFFFFu, s, o);
                c += __shfl_down_sync(0xFFFFFFFFu, c, o);
            }
            if (lane == 0) {
                out[0] = s / fmaxf(c, 1.0f);
                g_done = 0u;
            }
        }
    }
}

extern "C" void kernel_launch(void* const* d_in, const int* in_sizes, int n_in,
                              void* d_out, int out_size) {
    const float4* logits = (const float4*)d_in[0];
    const int*    labels = (const int*)d_in[1];
    const float*  cw     = (const float*)d_in[2];
    float*        out    = (float*)d_out;

    const int nrows = in_sizes[1] / S;   // B = 512

    prox_loss_kernel<<<nrows, TPB>>>(logits, labels, cw, out, nrows);
}

// round 8
// speedup vs baseline: 1.6026x; 1.6026x over previous
#include <cuda_runtime.h>
#include <cuda_bf16.h>

#define S        8192
#define TPB      512
#define CHUNKS   (S / TPB)          // 16 positions per thread
#define NWARP    (TPB / 32)         // 16 warps
#define NW       (S / 32)           // 256 mask words per row
#define MAXROWS  2048

__device__ float    g_partial[MAXROWS];
__device__ float    g_count[MAXROWS];
__device__ unsigned g_done;          // zero-init; self-resets every pass

__global__ __launch_bounds__(TPB)
void prox_loss_kernel(const float4* __restrict__ logits,
                      const int*    __restrict__ labels,
                      const float*  __restrict__ cw,
                      float*        __restrict__ out,
                      int nrows) {
    // M[0]=true2, M[1]=true3, M[2]=pred2, M[3]=pred3 (padded +1 both ends)
    __shared__ unsigned M[4][NW + 2];
    __shared__ float    ce_s[S];                 // 32 KB
    __shared__ float    lut[2048];               // f1 by 11-bit true-window
    __shared__ float    ws_sum[NWARP], ws_cnt[NWARP];
    __shared__ bool     s_is_last;

    const int row  = blockIdx.x;
    const int tid  = threadIdx.x;
    const int lane = tid & 31;
    const int warp = tid >> 5;

    const float NEG_LOG2_08 = -0.321928095f;     // log2(0.8)

    // ---- LUT + pad init (before the mask barrier) ----
    #pragma unroll
    for (int v = tid; v < 2048; v += TPB) {
        float f = 1.0f;
        if (!((v >> 5) & 1)) {                   // no true switch AT the position
            const unsigned fold = (__brev((unsigned)v & 31u) >> 27)
                                | (((unsigned)v >> 6) & 31u);  // bit(k-1)=dist k
            if (fold) f = exp2f((float)__ffs(fold) * NEG_LOG2_08);
        }
        lut[v] = f;
    }
    if (tid < 4) { M[tid][0] = 0u; M[tid][NW + 1] = 0u; }

    const float w0 = __ldg(&cw[0]);
    const float w1 = __ldg(&cw[1]);
    const float w2 = __ldg(&cw[2]);
    const float w3 = __ldg(&cw[3]);

    const float4* lg = logits + (size_t)row * S;
    const int*    lb = labels + (size_t)row * S;

    float cnt = 0.0f;
    bool  hasp2 = false, hasp3 = false;

    // ---- Phase 1: load, CE -> smem, class-2/3 pred bools, ballots -> smem ----
    #pragma unroll 4
    for (int c = 0; c < CHUNKS; c++) {
        const int p = c * TPB + tid;
        const float4 l = lg[p];
        const int    y = lb[p];

        // first-occurrence argmax membership for classes 2/3 only
        const bool gwz = l.w > l.z;
        const bool p3b = (l.w > l.x) & (l.w > l.y) & gwz;
        const bool p2b = (l.z > l.x) & (l.z > l.y) & !gwz;

        // softmax without max-subtraction (logits ~ N(0,1): no overflow risk)
        const float esum = __expf(l.x) + __expf(l.y) + __expf(l.z) + __expf(l.w);
        const float lse  = __logf(esum);

        const int ys = (y < 0) ? 0 : y;
        const float lya = (ys & 1) ? l.y : l.x;
        const float lyb = (ys & 1) ? l.w : l.z;
        const float ly  = (ys & 2) ? lyb : lya;
        const float wya = (ys & 1) ? w1 : w0;
        const float wyb = (ys & 1) ? w3 : w2;
        const float wy  = (ys & 2) ? wyb : wya;
        ce_s[p] = (y < 0) ? 0.0f : wy * (lse - ly);

        const bool t3b = (y == 3);
        const unsigned bt2 = __ballot_sync(0xFFFFFFFFu, y == 2);
        const unsigned bt3 = __ballot_sync(0xFFFFFFFFu, t3b);
        const unsigned bp2 = __ballot_sync(0xFFFFFFFFu, p2b);
        const unsigned bp3 = __ballot_sync(0xFFFFFFFFu, p3b);
        const unsigned bv  = __ballot_sync(0xFFFFFFFFu, y >= 0);
        hasp2 |= (bp2 != 0u);
        hasp3 |= (bp3 != 0u);
        if (lane == 0) {
            const int wi = (p >> 5) + 1;
            M[0][wi] = bt2; M[1][wi] = bt3; M[2][wi] = bp2; M[3][wi] = bp3;
            cnt += (float)__popc(bv);
        }
    }

    const int any2 = __syncthreads_or(hasp2 ? 1 : 0);
    const int any3 = __syncthreads_or(hasp3 ? 1 : 0);

    float sum = 0.0f;

    // ---- Phase 2: lean per-position factor via windows + LUT ----
    #pragma unroll 4
    for (int c = 0; c < CHUNKS; c++) {
        const int p  = c * TPB + tid;
        const int wi = (p >> 5) + 1;             // warp-uniform padded word

        const unsigned t2c = M[0][wi], t3c = M[1][wi];
        const unsigned p2c = M[2][wi], p3c = M[3][wi];

        const unsigned y3 = (t3c >> lane) & 1u;
        const unsigned a3 = (p3c >> lane) & 1u;
        const unsigned tm = ((t2c | t3c) >> lane) & 1u;
        const unsigned pm = ((p2c | p3c) >> lane) & 1u;

        // 11-bit windows, start bit = p+27 in padded bitspace
        const int bpp = p + 27;
        const int wi0 = bpp >> 5;
        const int sh  = bpp & 31;

        // true-mask window of the PREDICTED class -> decay via LUT
        const unsigned tw = __funnelshift_r(M[a3][wi0], M[a3][wi0 + 1], sh) & 0x7FFu;
        // pred-mask window of the LABEL class (incl. center) -> tfac
        const unsigned pw = __funnelshift_r(M[2 + y3][wi0], M[2 + y3][wi0 + 1], sh) & 0x7FFu;

        const float f1 = pm ? lut[tw] : 1.0f;
        const int  anyc = y3 ? any3 : any2;
        const float f2 = tm ? (anyc ? (pw ? 1.0f : 1.5f) : 2.0f) : 1.0f;

        sum += ce_s[p] * (f1 * f2);
    }

    // ---- Block reduction ----
    #pragma unroll
    for (int o = 16; o > 0; o >>= 1)
        sum += __shfl_down_sync(0xFFFFFFFFu, sum, o);
    if (lane == 0) { ws_sum[warp] = sum; ws_cnt[warp] = cnt; }
    __syncthreads();
    if (warp == 0) {
        sum = (lane < NWARP) ? ws_sum[lane] : 0.0f;
        cnt = (lane < NWARP) ? ws_cnt[lane] : 0.0f;
        #pragma unroll
        for (int o = 8; o > 0; o >>= 1) {
            sum += __shfl_down_sync(0xFFFFFFFFu, sum, o);
            cnt += __shfl_down_sync(0xFFFFFFFFu, cnt, o);
        }
        if (lane == 0) {
            g_partial[row] = sum;
            g_count[row]   = cnt;
            __threadfence();
            const unsigned prev = atomicAdd(&g_done, 1u);
            s_is_last = (prev == (unsigned)(nrows - 1));
        }
    }
    __syncthreads();

    // ---- Last block: global reduce + divide, reset counter ----
    if (s_is_last) {
        float s = 0.0f, c = 0.0f;
        for (int i = tid; i < nrows; i += TPB) {
            s += *((volatile float*)&g_partial[i]);
            c += *((volatile float*)&g_count[i]);
        }
        #pragma unroll
        for (int o = 16; o > 0; o >>= 1) {
            s += __shfl_down_sync(0xFFFFFFFFu, s, o);
            c += __shfl_down_sync(0xFFFFFFFFu, c, o);
        }
        if (lane == 0) { ws_sum[warp] = s; ws_cnt[warp] = c; }
        __syncthreads();
        if (warp == 0) {
            s = (lane < NWARP) ? ws_sum[lane] : 0.0f;
            c = (lane < NWARP) ? ws_cnt[lane] : 0.0f;
            #pragma unroll
            for (int o = 8; o > 0; o >>= 1) {
                s += __shfl_down_sync(0xFFFFFFFFu, s, o);
                c += __shfl_down_sync(0xFFFFFFFFu, c, o);
            }
            if (lane == 0) {
                out[0] = s / fmaxf(c, 1.0f);
                g_done = 0u;
            }
        }
    }
}

extern "C" void kernel_launch(void* const* d_in, const int* in_sizes, int n_in,
                              void* d_out, int out_size) {
    const float4* logits = (const float4*)d_in[0];
    const int*    labels = (const int*)d_in[1];
    const float*  cw     = (const float*)d_in[2];
    float*        out    = (float*)d_out;

    const int nrows = in_sizes[1] / S;   // B = 512

    prox_loss_kernel<<<nrows, TPB>>>(logits, labels, cw, out, nrows);
}